// round 13
// baseline (speedup 1.0000x reference)
#include <cuda_runtime.h>
#include <cuda_bf16.h>
#include <math.h>

#define SEQ_LEN 16384
#define ENC_H   2048
#define DEC_H   2048

#define RA      16                      // rows per fused block
#define NBLK    (SEQ_LEN / RA)          // 1024 blocks
#define VBLK    128                     // blocks that also compute v
#define RV      (ENC_H / VBLK)          // 16 v-rows per producer block

// Scratch (device globals — no allocation allowed)
__device__ float g_v[ENC_H];
__device__ float g_ctx[NBLK * ENC_H];    // 8 MB per-block partial contexts
__device__ float g_m[NBLK];
__device__ float g_z[NBLK];
__device__ unsigned int g_vdone;         // reset via cudaMemsetAsync each call

// ---------------------------------------------------------------------------
// kAll: blocks 0..127 first compute their 16 v-rows (W @ dec) and arrive on
// a flag. ALL blocks then issue their 32 enc LDG.128s, and only AFTER the
// loads are in flight do they wait on the flag (spin overlaps DRAM latency).
// ---------------------------------------------------------------------------
__global__ __launch_bounds__(256, 1) void kAll(const float* __restrict__ enc,
                                               const float* __restrict__ W,
                                               const float* __restrict__ dec) {
    __shared__ float s_red[8][RA];
    int t    = threadIdx.x;
    int warp = t >> 5;
    int lane = t & 31;

    // ---- phase V: producer blocks compute 16 rows of v = W @ dec ----
    if (blockIdx.x < VBLK) {
        size_t v0r = (size_t)blockIdx.x * RV;
        const float4* d4 = reinterpret_cast<const float4*>(dec);
        float4 u0 = __ldg(&d4[t]);
        float4 u1 = __ldg(&d4[t + 256]);

        float4 w0[RV], w1[RV];
        #pragma unroll
        for (int r = 0; r < RV; ++r) {
            const float4* row = reinterpret_cast<const float4*>(W + (v0r + r) * DEC_H);
            w0[r] = row[t];
            w1[r] = row[t + 256];
        }
        #pragma unroll
        for (int r = 0; r < RV; ++r) {
            float d = w0[r].x * u0.x + w0[r].y * u0.y + w0[r].z * u0.z + w0[r].w * u0.w
                    + w1[r].x * u1.x + w1[r].y * u1.y + w1[r].z * u1.z + w1[r].w * u1.w;
            #pragma unroll
            for (int o = 16; o > 0; o >>= 1) d += __shfl_xor_sync(0xffffffffu, d, o);
            if (lane == 0) s_red[warp][r] = d;
        }
        __syncthreads();
        if (t < RV) {
            float x = 0.0f;
            #pragma unroll
            for (int w = 0; w < 8; ++w) x += s_red[w][t];
            g_v[v0r + t] = x;
        }
        __threadfence();
        __syncthreads();
        if (t == 0) atomicAdd(&g_vdone, 1u);
        __syncthreads();               // s_red reused below
    }

    // ---- issue enc loads FIRST (overlap DRAM latency with the wait) ----
    size_t s0 = (size_t)blockIdx.x * RA;
    float4 r0[RA], r1[RA];
    #pragma unroll
    for (int r = 0; r < RA; ++r) {
        const float4* row = reinterpret_cast<const float4*>(enc + (s0 + r) * ENC_H);
        r0[r] = row[t];
        r1[r] = row[t + 256];
    }

    // ---- wait for complete v ----
    if (t == 0) {
        while (*(volatile unsigned int*)&g_vdone < VBLK) __nanosleep(64);
    }
    __syncthreads();
    __threadfence();

    const float4* v4 = reinterpret_cast<const float4*>(g_v);
    float4 v0 = v4[t];
    float4 v1 = v4[t + 256];

    #pragma unroll
    for (int r = 0; r < RA; ++r) {
        float d = r0[r].x * v0.x + r0[r].y * v0.y + r0[r].z * v0.z + r0[r].w * v0.w
                + r1[r].x * v1.x + r1[r].y * v1.y + r1[r].z * v1.z + r1[r].w * v1.w;
        #pragma unroll
        for (int o = 16; o > 0; o >>= 1) d += __shfl_xor_sync(0xffffffffu, d, o);
        if (lane == 0) s_red[warp][r] = d;
    }
    __syncthreads();

    float sc[RA];
    #pragma unroll
    for (int r = 0; r < RA; ++r) {
        float x = 0.0f;
        #pragma unroll
        for (int w = 0; w < 8; ++w) x += s_red[w][r];
        sc[r] = x;
    }
    float m = sc[0];
    #pragma unroll
    for (int r = 1; r < RA; ++r) m = fmaxf(m, sc[r]);
    float z = 0.0f;
    float w[RA];
    #pragma unroll
    for (int r = 0; r < RA; ++r) { w[r] = __expf(sc[r] - m); z += w[r]; }

    float4 a0 = make_float4(0.f, 0.f, 0.f, 0.f);
    float4 a1 = make_float4(0.f, 0.f, 0.f, 0.f);
    #pragma unroll
    for (int r = 0; r < RA; ++r) {
        a0.x += w[r] * r0[r].x; a0.y += w[r] * r0[r].y;
        a0.z += w[r] * r0[r].z; a0.w += w[r] * r0[r].w;
        a1.x += w[r] * r1[r].x; a1.y += w[r] * r1[r].y;
        a1.z += w[r] * r1[r].z; a1.w += w[r] * r1[r].w;
    }

    float4* ctx = reinterpret_cast<float4*>(g_ctx + (size_t)blockIdx.x * ENC_H);
    ctx[t] = a0;
    ctx[t + 256] = a1;
    if (t == 0) { g_m[blockIdx.x] = m; g_z[blockIdx.x] = z; }
}

// ---------------------------------------------------------------------------
// Kernel B: single-kernel combine over NBLK=1024 partials (R11 shape).
// ---------------------------------------------------------------------------
__global__ __launch_bounds__(256) void kB_combine(float* __restrict__ out) {
    __shared__ float s_e[NBLK];          // 4 KB
    __shared__ float s_red[8];
    __shared__ float s_M, s_invZ;
    __shared__ float4 s_out[8];
    int t    = threadIdx.x;
    int warp = t >> 5;
    int lane = t & 31;

    float m = fmaxf(g_m[t], fmaxf(g_m[t + 256], fmaxf(g_m[t + 512], g_m[t + 768])));
    #pragma unroll
    for (int o = 16; o > 0; o >>= 1) m = fmaxf(m, __shfl_xor_sync(0xffffffffu, m, o));
    if (lane == 0) s_red[warp] = m;
    __syncthreads();
    if (t == 0) {
        float mm = s_red[0];
        #pragma unroll
        for (int wdx = 1; wdx < 8; ++wdx) mm = fmaxf(mm, s_red[wdx]);
        s_M = mm;
    }
    __syncthreads();
    float M = s_M;

    float zs = 0.0f;
    #pragma unroll
    for (int i = 0; i < NBLK / 256; ++i) {
        int b = t + 256 * i;
        float e = __expf(g_m[b] - M);
        s_e[b] = e;
        zs += e * g_z[b];
    }
    #pragma unroll
    for (int o = 16; o > 0; o >>= 1) zs += __shfl_xor_sync(0xffffffffu, zs, o);
    __syncthreads();
    if (lane == 0) s_red[warp] = zs;
    __syncthreads();
    if (t == 0) {
        float s = 0.0f;
        #pragma unroll
        for (int wdx = 0; wdx < 8; ++wdx) s += s_red[wdx];
        s_invZ = 1.0f / s;
    }
    __syncthreads();

    int col4 = blockIdx.x * 4 + (warp >> 1);     // [0, 512)
    int half = warp & 1;
    const float4* ctx = reinterpret_cast<const float4*>(g_ctx);
    float4 acc = make_float4(0.f, 0.f, 0.f, 0.f);
    int b0 = half * (NBLK / 2) + lane;
    #pragma unroll 8
    for (int b = b0; b < half * (NBLK / 2) + NBLK / 2; b += 32) {
        float e  = s_e[b];
        float4 c = ctx[(size_t)b * (ENC_H / 4) + col4];
        acc.x += e * c.x; acc.y += e * c.y; acc.z += e * c.z; acc.w += e * c.w;
    }
    #pragma unroll
    for (int o = 16; o > 0; o >>= 1) {
        acc.x += __shfl_xor_sync(0xffffffffu, acc.x, o);
        acc.y += __shfl_xor_sync(0xffffffffu, acc.y, o);
        acc.z += __shfl_xor_sync(0xffffffffu, acc.z, o);
        acc.w += __shfl_xor_sync(0xffffffffu, acc.w, o);
    }
    if (lane == 0) s_out[warp] = acc;
    __syncthreads();
    if (t < 4) {
        float4 a = s_out[2 * t], b = s_out[2 * t + 1];
        float inv = s_invZ;
        float4 r;
        r.x = (a.x + b.x) * inv;
        r.y = (a.y + b.y) * inv;
        r.z = (a.z + b.z) * inv;
        r.w = (a.w + b.w) * inv;
        reinterpret_cast<float4*>(out)[blockIdx.x * 4 + t] = r;
    }
}

extern "C" void kernel_launch(void* const* d_in, const int* in_sizes, int n_in,
                              void* d_out, int out_size) {
    const float* enc = (const float*)d_in[0];   // [16384, 2048]
    const float* dec = (const float*)d_in[1];   // [1, 2048]
    const float* W   = (const float*)d_in[2];   // [2048, 2048]
    float* out = (float*)d_out;                 // [1, 2048]

    static void* vdone_addr = nullptr;
    if (!vdone_addr) cudaGetSymbolAddress(&vdone_addr, g_vdone);

    cudaMemsetAsync(vdone_addr, 0, sizeof(unsigned int));
    kAll<<<NBLK, 256>>>(enc, W, dec);
    kB_combine<<<128, 256>>>(out);
}

// round 15
// speedup vs baseline: 1.4472x; 1.4472x over previous
#include <cuda_runtime.h>
#include <cuda_bf16.h>
#include <math.h>

#define SEQ_LEN 16384
#define ENC_H   2048
#define DEC_H   2048

#define RA      16                      // rows per kA block
#define NBLK    (SEQ_LEN / RA)          // 1024 kA blocks
#define R1      4                       // rows per k1 block
#define N1BLK   (ENC_H / R1)            // 512 k1 blocks

// Scratch (device globals — no allocation allowed)
__device__ float g_v[ENC_H];
__device__ float g_ctx[NBLK * ENC_H];    // 8 MB per-block partial contexts
__device__ float g_m[NBLK];
__device__ float g_z[NBLK];

// ---------------------------------------------------------------------------
// Kernel 1: v = W @ dec (R11-proven). Triggers programmatic completion.
// ---------------------------------------------------------------------------
__global__ __launch_bounds__(256) void k1_gemv(const float* __restrict__ W,
                                               const float* __restrict__ dec) {
    __shared__ float s_red[8][R1];
    int t    = threadIdx.x;
    int warp = t >> 5;
    int lane = t & 31;
    size_t s0 = (size_t)blockIdx.x * R1;

    const float4* d4 = reinterpret_cast<const float4*>(dec);
    float4 v0 = __ldg(&d4[t]);
    float4 v1 = __ldg(&d4[t + 256]);

    float4 r0[R1], r1[R1];
    #pragma unroll
    for (int r = 0; r < R1; ++r) {
        const float4* row = reinterpret_cast<const float4*>(W + (s0 + r) * DEC_H);
        r0[r] = row[t];
        r1[r] = row[t + 256];
    }

    #pragma unroll
    for (int r = 0; r < R1; ++r) {
        float d = r0[r].x * v0.x + r0[r].y * v0.y + r0[r].z * v0.z + r0[r].w * v0.w
                + r1[r].x * v1.x + r1[r].y * v1.y + r1[r].z * v1.z + r1[r].w * v1.w;
        #pragma unroll
        for (int o = 16; o > 0; o >>= 1) d += __shfl_xor_sync(0xffffffffu, d, o);
        if (lane == 0) s_red[warp][r] = d;
    }
    __syncthreads();
    if (t < R1) {
        float x = 0.0f;
        #pragma unroll
        for (int w = 0; w < 8; ++w) x += s_red[w][t];
        g_v[s0 + t] = x;
    }
    cudaTriggerProgrammaticLaunchCompletion();
}

// ---------------------------------------------------------------------------
// Kernel A (R11-proven body): issues its 32 enc LDG.128s FIRST, then the
// HW grid-dependency sync (overlaps k1 tail), then reads g_v and proceeds.
// ---------------------------------------------------------------------------
__global__ __launch_bounds__(256, 1) void kA_fused(const float* __restrict__ enc) {
    __shared__ float s_red[8][RA];
    int t    = threadIdx.x;
    int warp = t >> 5;
    int lane = t & 31;
    size_t s0 = (size_t)blockIdx.x * RA;

    // enc loads first — independent of k1's output
    float4 r0[RA], r1[RA];
    #pragma unroll
    for (int r = 0; r < RA; ++r) {
        const float4* row = reinterpret_cast<const float4*>(enc + (s0 + r) * ENC_H);
        r0[r] = row[t];
        r1[r] = row[t + 256];
    }

    // wait for k1 grid completion (HW-managed, memory flushed)
    cudaGridDependencySynchronize();

    const float4* v4 = reinterpret_cast<const float4*>(g_v);
    float4 v0 = v4[t];
    float4 v1 = v4[t + 256];

    #pragma unroll
    for (int r = 0; r < RA; ++r) {
        float d = r0[r].x * v0.x + r0[r].y * v0.y + r0[r].z * v0.z + r0[r].w * v0.w
                + r1[r].x * v1.x + r1[r].y * v1.y + r1[r].z * v1.z + r1[r].w * v1.w;
        #pragma unroll
        for (int o = 16; o > 0; o >>= 1) d += __shfl_xor_sync(0xffffffffu, d, o);
        if (lane == 0) s_red[warp][r] = d;
    }
    __syncthreads();

    float sc[RA];
    #pragma unroll
    for (int r = 0; r < RA; ++r) {
        float x = 0.0f;
        #pragma unroll
        for (int w = 0; w < 8; ++w) x += s_red[w][r];
        sc[r] = x;
    }
    float m = sc[0];
    #pragma unroll
    for (int r = 1; r < RA; ++r) m = fmaxf(m, sc[r]);
    float z = 0.0f;
    float w[RA];
    #pragma unroll
    for (int r = 0; r < RA; ++r) { w[r] = __expf(sc[r] - m); z += w[r]; }

    float4 a0 = make_float4(0.f, 0.f, 0.f, 0.f);
    float4 a1 = make_float4(0.f, 0.f, 0.f, 0.f);
    #pragma unroll
    for (int r = 0; r < RA; ++r) {
        a0.x += w[r] * r0[r].x; a0.y += w[r] * r0[r].y;
        a0.z += w[r] * r0[r].z; a0.w += w[r] * r0[r].w;
        a1.x += w[r] * r1[r].x; a1.y += w[r] * r1[r].y;
        a1.z += w[r] * r1[r].z; a1.w += w[r] * r1[r].w;
    }

    float4* ctx = reinterpret_cast<float4*>(g_ctx + (size_t)blockIdx.x * ENC_H);
    ctx[t] = a0;
    ctx[t + 256] = a1;
    if (t == 0) { g_m[blockIdx.x] = m; g_z[blockIdx.x] = z; }
    cudaTriggerProgrammaticLaunchCompletion();
}

// ---------------------------------------------------------------------------
// Kernel B (R11-proven): single-kernel combine; grid-syncs first.
// ---------------------------------------------------------------------------
__global__ __launch_bounds__(256) void kB_combine(float* __restrict__ out) {
    __shared__ float s_e[NBLK];          // 4 KB
    __shared__ float s_red[8];
    __shared__ float s_M, s_invZ;
    __shared__ float4 s_out[8];
    int t    = threadIdx.x;
    int warp = t >> 5;
    int lane = t & 31;

    cudaGridDependencySynchronize();

    float m = fmaxf(g_m[t], fmaxf(g_m[t + 256], fmaxf(g_m[t + 512], g_m[t + 768])));
    #pragma unroll
    for (int o = 16; o > 0; o >>= 1) m = fmaxf(m, __shfl_xor_sync(0xffffffffu, m, o));
    if (lane == 0) s_red[warp] = m;
    __syncthreads();
    if (t == 0) {
        float mm = s_red[0];
        #pragma unroll
        for (int wdx = 1; wdx < 8; ++wdx) mm = fmaxf(mm, s_red[wdx]);
        s_M = mm;
    }
    __syncthreads();
    float M = s_M;

    float zs = 0.0f;
    #pragma unroll
    for (int i = 0; i < NBLK / 256; ++i) {
        int b = t + 256 * i;
        float e = __expf(g_m[b] - M);
        s_e[b] = e;
        zs += e * g_z[b];
    }
    #pragma unroll
    for (int o = 16; o > 0; o >>= 1) zs += __shfl_xor_sync(0xffffffffu, zs, o);
    __syncthreads();
    if (lane == 0) s_red[warp] = zs;
    __syncthreads();
    if (t == 0) {
        float s = 0.0f;
        #pragma unroll
        for (int wdx = 0; wdx < 8; ++wdx) s += s_red[wdx];
        s_invZ = 1.0f / s;
    }
    __syncthreads();

    int col4 = blockIdx.x * 4 + (warp >> 1);     // [0, 512)
    int half = warp & 1;
    const float4* ctx = reinterpret_cast<const float4*>(g_ctx);
    float4 acc = make_float4(0.f, 0.f, 0.f, 0.f);
    int b0 = half * (NBLK / 2) + lane;
    #pragma unroll 8
    for (int b = b0; b < half * (NBLK / 2) + NBLK / 2; b += 32) {
        float e  = s_e[b];
        float4 c = ctx[(size_t)b * (ENC_H / 4) + col4];
        acc.x += e * c.x; acc.y += e * c.y; acc.z += e * c.z; acc.w += e * c.w;
    }
    #pragma unroll
    for (int o = 16; o > 0; o >>= 1) {
        acc.x += __shfl_xor_sync(0xffffffffu, acc.x, o);
        acc.y += __shfl_xor_sync(0xffffffffu, acc.y, o);
        acc.z += __shfl_xor_sync(0xffffffffu, acc.z, o);
        acc.w += __shfl_xor_sync(0xffffffffu, acc.w, o);
    }
    if (lane == 0) s_out[warp] = acc;
    __syncthreads();
    if (t < 4) {
        float4 a = s_out[2 * t], b = s_out[2 * t + 1];
        float inv = s_invZ;
        float4 r;
        r.x = (a.x + b.x) * inv;
        r.y = (a.y + b.y) * inv;
        r.z = (a.z + b.z) * inv;
        r.w = (a.w + b.w) * inv;
        reinterpret_cast<float4*>(out)[blockIdx.x * 4 + t] = r;
    }
}

// ---------------------------------------------------------------------------
// Launch: k1 normal; kA and kB with programmatic stream serialization (PDL).
// ---------------------------------------------------------------------------
static void launch_pdl(void* func, dim3 grid, dim3 block, void** args) {
    cudaLaunchConfig_t cfg = {};
    cfg.gridDim = grid;
    cfg.blockDim = block;
    cfg.stream = 0;
    cudaLaunchAttribute attr[1];
    attr[0].id = cudaLaunchAttributeProgrammaticStreamSerialization;
    attr[0].val.programmaticStreamSerializationAllowed = 1;
    cfg.attrs = attr;
    cfg.numAttrs = 1;
    cudaLaunchKernelExC(&cfg, func, args);
}

extern "C" void kernel_launch(void* const* d_in, const int* in_sizes, int n_in,
                              void* d_out, int out_size) {
    const float* enc = (const float*)d_in[0];   // [16384, 2048]
    const float* dec = (const float*)d_in[1];   // [1, 2048]
    const float* W   = (const float*)d_in[2];   // [2048, 2048]
    float* out = (float*)d_out;                 // [1, 2048]

    k1_gemv<<<N1BLK, 256>>>(W, dec);

    {
        void* args[] = { (void*)&enc };
        launch_pdl((void*)kA_fused, dim3(NBLK), dim3(256), args);
    }
    {
        void* args[] = { (void*)&out };
        launch_pdl((void*)kB_combine, dim3(128), dim3(256), args);
    }
}

// round 16
// speedup vs baseline: 1.5682x; 1.0836x over previous
#include <cuda_runtime.h>
#include <cuda_bf16.h>
#include <math.h>
#include <cstdint>

#define SEQ_LEN 16384
#define ENC_H   2048
#define DEC_H   2048

#define RA      16                      // rows per kA block
#define RREG    8                       // rows kept in registers
#define RSM     (RA - RREG)             // rows staged in smem
#define NBLK    (SEQ_LEN / RA)          // 1024 kA blocks
#define R1      4                       // rows per k1 block
#define N1BLK   (ENC_H / R1)            // 512 k1 blocks
#define SMEM_BYTES (RSM * ENC_H * 4)    // 64 KB dynamic smem

// Scratch (device globals — no allocation allowed)
__device__ float g_v[ENC_H];
__device__ float g_ctx[NBLK * ENC_H];    // 8 MB per-block partial contexts
__device__ float g_m[NBLK];
__device__ float g_z[NBLK];

// ---------------------------------------------------------------------------
// Kernel 1: v = W @ dec (R11-proven). Triggers programmatic completion.
// ---------------------------------------------------------------------------
__global__ __launch_bounds__(256) void k1_gemv(const float* __restrict__ W,
                                               const float* __restrict__ dec) {
    __shared__ float s_red[8][R1];
    int t    = threadIdx.x;
    int warp = t >> 5;
    int lane = t & 31;
    size_t s0 = (size_t)blockIdx.x * R1;

    const float4* d4 = reinterpret_cast<const float4*>(dec);
    float4 v0 = __ldg(&d4[t]);
    float4 v1 = __ldg(&d4[t + 256]);

    float4 r0[R1], r1[R1];
    #pragma unroll
    for (int r = 0; r < R1; ++r) {
        const float4* row = reinterpret_cast<const float4*>(W + (s0 + r) * DEC_H);
        r0[r] = row[t];
        r1[r] = row[t + 256];
    }

    #pragma unroll
    for (int r = 0; r < R1; ++r) {
        float d = r0[r].x * v0.x + r0[r].y * v0.y + r0[r].z * v0.z + r0[r].w * v0.w
                + r1[r].x * v1.x + r1[r].y * v1.y + r1[r].z * v1.z + r1[r].w * v1.w;
        #pragma unroll
        for (int o = 16; o > 0; o >>= 1) d += __shfl_xor_sync(0xffffffffu, d, o);
        if (lane == 0) s_red[warp][r] = d;
    }
    __syncthreads();
    if (t < R1) {
        float x = 0.0f;
        #pragma unroll
        for (int w = 0; w < 8; ++w) x += s_red[w][t];
        g_v[s0 + t] = x;
    }
    cudaTriggerProgrammaticLaunchCompletion();
}

// ---------------------------------------------------------------------------
// Kernel A: RA=16 at occ 2. Rows 0-7 in registers; rows 8-15 via cp.async
// into 64 KB dynamic smem (each thread copies exactly the elements it later
// reads -> wait_group 0 is sufficient, no extra barrier). 2 blocks/SM let
// one block's loads overlap the other's compute.
// ---------------------------------------------------------------------------
__global__ __launch_bounds__(256, 2) void kA_fused(const float* __restrict__ enc) {
    extern __shared__ float s_data[];          // RSM rows x 2048 floats
    __shared__ float s_red[8][RA];
    int t    = threadIdx.x;
    int warp = t >> 5;
    int lane = t & 31;
    size_t s0 = (size_t)blockIdx.x * RA;

    // --- stage rows 8-15 into smem via cp.async (issued first) ---
    uint32_t sbase = (uint32_t)__cvta_generic_to_shared(s_data);
    #pragma unroll
    for (int r = 0; r < RSM; ++r) {
        const float4* row = reinterpret_cast<const float4*>(
            enc + (s0 + RREG + r) * ENC_H);
        uint32_t d0 = sbase + (r * 512 + t) * 16;
        uint32_t d1 = sbase + (r * 512 + t + 256) * 16;
        asm volatile("cp.async.cg.shared.global [%0], [%1], 16;"
                     :: "r"(d0), "l"(row + t) : "memory");
        asm volatile("cp.async.cg.shared.global [%0], [%1], 16;"
                     :: "r"(d1), "l"(row + t + 256) : "memory");
    }
    asm volatile("cp.async.commit_group;" ::: "memory");

    // --- rows 0-7 into registers ---
    float4 r0[RREG], r1[RREG];
    #pragma unroll
    for (int r = 0; r < RREG; ++r) {
        const float4* row = reinterpret_cast<const float4*>(enc + (s0 + r) * ENC_H);
        r0[r] = row[t];
        r1[r] = row[t + 256];
    }

    // wait for k1 (loads above are independent of it)
    cudaGridDependencySynchronize();

    const float4* v4 = reinterpret_cast<const float4*>(g_v);
    float4 v0 = v4[t];
    float4 v1 = v4[t + 256];

    float d[RA];
    #pragma unroll
    for (int r = 0; r < RREG; ++r) {
        d[r] = r0[r].x * v0.x + r0[r].y * v0.y + r0[r].z * v0.z + r0[r].w * v0.w
             + r1[r].x * v1.x + r1[r].y * v1.y + r1[r].z * v1.z + r1[r].w * v1.w;
    }

    // smem rows ready for this thread after wait_group 0 (own data only)
    asm volatile("cp.async.wait_group 0;" ::: "memory");
    const float4* s4 = reinterpret_cast<const float4*>(s_data);
    #pragma unroll
    for (int r = 0; r < RSM; ++r) {
        float4 x0 = s4[r * 512 + t];
        float4 x1 = s4[r * 512 + t + 256];
        d[RREG + r] = x0.x * v0.x + x0.y * v0.y + x0.z * v0.z + x0.w * v0.w
                    + x1.x * v1.x + x1.y * v1.y + x1.z * v1.z + x1.w * v1.w;
    }

    #pragma unroll
    for (int r = 0; r < RA; ++r) {
        float x = d[r];
        #pragma unroll
        for (int o = 16; o > 0; o >>= 1) x += __shfl_xor_sync(0xffffffffu, x, o);
        if (lane == 0) s_red[warp][r] = x;
    }
    __syncthreads();

    float sc[RA];
    #pragma unroll
    for (int r = 0; r < RA; ++r) {
        float x = 0.0f;
        #pragma unroll
        for (int w = 0; w < 8; ++w) x += s_red[w][r];
        sc[r] = x;
    }
    float m = sc[0];
    #pragma unroll
    for (int r = 1; r < RA; ++r) m = fmaxf(m, sc[r]);

    float z = 0.0f;
    float4 a0 = make_float4(0.f, 0.f, 0.f, 0.f);
    float4 a1 = make_float4(0.f, 0.f, 0.f, 0.f);
    #pragma unroll
    for (int r = 0; r < RREG; ++r) {
        float w = __expf(sc[r] - m);
        z += w;
        a0.x += w * r0[r].x; a0.y += w * r0[r].y;
        a0.z += w * r0[r].z; a0.w += w * r0[r].w;
        a1.x += w * r1[r].x; a1.y += w * r1[r].y;
        a1.z += w * r1[r].z; a1.w += w * r1[r].w;
    }
    #pragma unroll
    for (int r = 0; r < RSM; ++r) {
        float w = __expf(sc[RREG + r] - m);
        z += w;
        float4 x0 = s4[r * 512 + t];
        float4 x1 = s4[r * 512 + t + 256];
        a0.x += w * x0.x; a0.y += w * x0.y; a0.z += w * x0.z; a0.w += w * x0.w;
        a1.x += w * x1.x; a1.y += w * x1.y; a1.z += w * x1.z; a1.w += w * x1.w;
    }

    float4* ctx = reinterpret_cast<float4*>(g_ctx + (size_t)blockIdx.x * ENC_H);
    ctx[t] = a0;
    ctx[t + 256] = a1;
    if (t == 0) { g_m[blockIdx.x] = m; g_z[blockIdx.x] = z; }
    cudaTriggerProgrammaticLaunchCompletion();
}

// ---------------------------------------------------------------------------
// Kernel B (R11-proven): single-kernel combine; grid-syncs first.
// ---------------------------------------------------------------------------
__global__ __launch_bounds__(256) void kB_combine(float* __restrict__ out) {
    __shared__ float s_e[NBLK];          // 4 KB
    __shared__ float s_red[8];
    __shared__ float s_M, s_invZ;
    __shared__ float4 s_out[8];
    int t    = threadIdx.x;
    int warp = t >> 5;
    int lane = t & 31;

    cudaGridDependencySynchronize();

    float m = fmaxf(g_m[t], fmaxf(g_m[t + 256], fmaxf(g_m[t + 512], g_m[t + 768])));
    #pragma unroll
    for (int o = 16; o > 0; o >>= 1) m = fmaxf(m, __shfl_xor_sync(0xffffffffu, m, o));
    if (lane == 0) s_red[warp] = m;
    __syncthreads();
    if (t == 0) {
        float mm = s_red[0];
        #pragma unroll
        for (int wdx = 1; wdx < 8; ++wdx) mm = fmaxf(mm, s_red[wdx]);
        s_M = mm;
    }
    __syncthreads();
    float M = s_M;

    float zs = 0.0f;
    #pragma unroll
    for (int i = 0; i < NBLK / 256; ++i) {
        int b = t + 256 * i;
        float e = __expf(g_m[b] - M);
        s_e[b] = e;
        zs += e * g_z[b];
    }
    #pragma unroll
    for (int o = 16; o > 0; o >>= 1) zs += __shfl_xor_sync(0xffffffffu, zs, o);
    __syncthreads();
    if (lane == 0) s_red[warp] = zs;
    __syncthreads();
    if (t == 0) {
        float s = 0.0f;
        #pragma unroll
        for (int wdx = 0; wdx < 8; ++wdx) s += s_red[wdx];
        s_invZ = 1.0f / s;
    }
    __syncthreads();

    int col4 = blockIdx.x * 4 + (warp >> 1);     // [0, 512)
    int half = warp & 1;
    const float4* ctx = reinterpret_cast<const float4*>(g_ctx);
    float4 acc = make_float4(0.f, 0.f, 0.f, 0.f);
    int b0 = half * (NBLK / 2) + lane;
    #pragma unroll 8
    for (int b = b0; b < half * (NBLK / 2) + NBLK / 2; b += 32) {
        float e  = s_e[b];
        float4 c = ctx[(size_t)b * (ENC_H / 4) + col4];
        acc.x += e * c.x; acc.y += e * c.y; acc.z += e * c.z; acc.w += e * c.w;
    }
    #pragma unroll
    for (int o = 16; o > 0; o >>= 1) {
        acc.x += __shfl_xor_sync(0xffffffffu, acc.x, o);
        acc.y += __shfl_xor_sync(0xffffffffu, acc.y, o);
        acc.z += __shfl_xor_sync(0xffffffffu, acc.z, o);
        acc.w += __shfl_xor_sync(0xffffffffu, acc.w, o);
    }
    if (lane == 0) s_out[warp] = acc;
    __syncthreads();
    if (t < 4) {
        float4 a = s_out[2 * t], b = s_out[2 * t + 1];
        float inv = s_invZ;
        float4 r;
        r.x = (a.x + b.x) * inv;
        r.y = (a.y + b.y) * inv;
        r.z = (a.z + b.z) * inv;
        r.w = (a.w + b.w) * inv;
        reinterpret_cast<float4*>(out)[blockIdx.x * 4 + t] = r;
    }
}

// ---------------------------------------------------------------------------
// Launch: k1 normal; kA and kB with programmatic stream serialization (PDL).
// ---------------------------------------------------------------------------
static void launch_pdl(void* func, dim3 grid, dim3 block, void** args,
                       size_t smem) {
    cudaLaunchConfig_t cfg = {};
    cfg.gridDim = grid;
    cfg.blockDim = block;
    cfg.dynamicSmemBytes = smem;
    cfg.stream = 0;
    cudaLaunchAttribute attr[1];
    attr[0].id = cudaLaunchAttributeProgrammaticStreamSerialization;
    attr[0].val.programmaticStreamSerializationAllowed = 1;
    cfg.attrs = attr;
    cfg.numAttrs = 1;
    cudaLaunchKernelExC(&cfg, func, args);
}

extern "C" void kernel_launch(void* const* d_in, const int* in_sizes, int n_in,
                              void* d_out, int out_size) {
    const float* enc = (const float*)d_in[0];   // [16384, 2048]
    const float* dec = (const float*)d_in[1];   // [1, 2048]
    const float* W   = (const float*)d_in[2];   // [2048, 2048]
    float* out = (float*)d_out;                 // [1, 2048]

    static bool attr_set = false;
    if (!attr_set) {
        cudaFuncSetAttribute(kA_fused, cudaFuncAttributeMaxDynamicSharedMemorySize,
                             SMEM_BYTES);
        attr_set = true;
    }

    k1_gemv<<<N1BLK, 256>>>(W, dec);

    {
        void* args[] = { (void*)&enc };
        launch_pdl((void*)kA_fused, dim3(NBLK), dim3(256), args, SMEM_BYTES);
    }
    {
        void* args[] = { (void*)&out };
        launch_pdl((void*)kB_combine, dim3(128), dim3(256), args, 0);
    }
}